// round 9
// baseline (speedup 1.0000x reference)
#include <cuda_runtime.h>
#include <cuda_fp16.h>
#include <float.h>
#include <stdint.h>

#define NROWS   262144
#define DIM     64
#define NCODES  512
#define NELEM   (NROWS * DIM)
#define TM      128
#define NTILES  (NROWS / TM)     // 2048
#define GRID    152
#define NTHREADS 256

#define RSTRIDE 72               // halves per padded row (144 B: conflict-free ldmatrix)

// SMEM byte offsets
#define SM_AH    0                       // A hi  [128][72] f16   (18432)
#define SM_BH    18432                   // B hi  [512][72] f16   (73728)
#define SM_BM    92160                   // B lo                  (73728)
#define SM_NS    165888                  // code norms f32[512]   (2048)
#define SM_RN    167936                  // row norms  f32[128]   (512)
#define SM_S1    168448                  // row sum|m_x| f32[128] (512)
#define SM_CODE  168960                  // codes int[128]        (512)
#define SM_RD1   169472                  // best  f32[128][8]     (4096)
#define SM_RDK   173568                  // bestk int[128][8]     (4096)
#define SM_RD2   177664                  // 2nd   f32[128][8]     (4096)
#define SM_SIZE  181760

__device__ float g_partials[GRID];
__device__ float g_ns[NCODES];
__device__ int   g_wcount;
__device__ float g_refine_loss;
__device__ int   g_work[NROWS];

__device__ __forceinline__ uint32_t smem_u32(const void* p) {
    uint32_t a;
    asm("{ .reg .u64 t; cvta.to.shared.u64 t, %1; cvt.u32.u64 %0, t; }" : "=r"(a) : "l"(p));
    return a;
}

#define LDSM4(r, addr) \
    asm volatile("ldmatrix.sync.aligned.m8n8.x4.shared.b16 {%0,%1,%2,%3}, [%4];" \
        : "=r"((r)[0]), "=r"((r)[1]), "=r"((r)[2]), "=r"((r)[3]) : "r"(addr))

#define MMA16816(c, a, b0, b1) \
    asm volatile("mma.sync.aligned.m16n8k16.row.col.f32.f16.f16.f32 " \
        "{%0,%1,%2,%3}, {%4,%5,%6,%7}, {%8,%9}, {%0,%1,%2,%3};" \
        : "+f"((c)[0]), "+f"((c)[1]), "+f"((c)[2]), "+f"((c)[3]) \
        : "r"((a)[0]), "r"((a)[1]), "r"((a)[2]), "r"((a)[3]), "r"(b0), "r"(b1))

extern __shared__ char smem_raw[];

__global__ void zero_kernel() {
    g_wcount = 0;
    g_refine_loss = 0.0f;
}

__global__ __launch_bounds__(NTHREADS, 1) void vq_kernel(
    const float* __restrict__ x, const float* __restrict__ dict,
    float* __restrict__ out)
{
    char* sm = smem_raw;
    const uint32_t smu = smem_u32(sm);

    __half* Bh      = (__half*)(sm + SM_BH);
    __half* Bm      = (__half*)(sm + SM_BM);
    __half* Ah      = (__half*)(sm + SM_AH);
    float*  ns_s    = (float*)(sm + SM_NS);
    float*  rn_s    = (float*)(sm + SM_RN);
    float*  s1_s    = (float*)(sm + SM_S1);
    int*    codes_s = (int*)(sm + SM_CODE);
    float*  rd1     = (float*)(sm + SM_RD1);
    int*    rdk     = (int*)(sm + SM_RDK);
    float*  rd2     = (float*)(sm + SM_RD2);

    const int tid  = threadIdx.x;
    const int w    = tid >> 5;
    const int lane = tid & 31;

    // ---- build codebook splits in SMEM (dict is [D=64][K=512], k fastest) ----
    {
        const float4* d4 = (const float4*)dict;
        for (int i = tid; i < 64 * 128; i += NTHREADS) {
            int d = i >> 7, kq = i & 127;
            float4 v = d4[d * 128 + kq];
            float vv[4] = {v.x, v.y, v.z, v.w};
            #pragma unroll
            for (int j = 0; j < 4; j++) {
                int k = kq * 4 + j;
                __half h = __float2half_rn(vv[j]);
                __half m = __float2half_rn(vv[j] - __half2float(h));
                Bh[k * RSTRIDE + d] = h;
                Bm[k * RSTRIDE + d] = m;
            }
        }
        for (int k = tid; k < NCODES; k += NTHREADS) {
            float s = 0.0f;
            #pragma unroll 8
            for (int d = 0; d < DIM; d++) {
                float v = dict[d * NCODES + k];
                s = fmaf(v, v, s);
            }
            ns_s[k] = s;
            if (blockIdx.x == 0) g_ns[k] = s;
        }
    }
    __syncthreads();

    // lane-constant fragment addressing
    const int arow = (lane & 7) + (lane & 8);
    const int bn   = (lane & 7) + ((lane & 16) >> 1);
    const int bk   = (lane & 8);
    const int acol = (lane & 16) ? 8 : 0;
    const int crow = lane >> 2;
    const int ccol = 2 * (lane & 3);

    // ---- B-stationary: each warp owns codes [w*64, w*64+64) in registers ----
    uint32_t BHf[4][4][4];
    uint32_t BMf[4][4][4];
    {
        const uint32_t bHbase = smu + SM_BH + (uint32_t)((w * 64 + bn) * RSTRIDE + bk) * 2;
        const uint32_t bMbase = bHbase + (SM_BM - SM_BH);
        #pragma unroll
        for (int p = 0; p < 4; p++)
            #pragma unroll
            for (int kc = 0; kc < 4; kc++) {
                uint32_t o = (uint32_t)(p * 16) * (RSTRIDE * 2) + kc * 32;
                LDSM4(BHf[p][kc], bHbase + o);
                LDSM4(BMf[p][kc], bMbase + o);
            }
    }

    float nk0_r[8], nk1_r[8];
    #pragma unroll
    for (int nt = 0; nt < 8; nt++) {
        int n = w * 64 + nt * 8 + ccol;
        nk0_r[nt] = ns_s[n];
        nk1_r[nt] = ns_s[n + 1];
    }

    const uint32_t aHbase0 = smu + SM_AH + (uint32_t)(arow * RSTRIDE + acol) * 2;

    const int r2 = tid >> 1;
    const int ch = tid & 1;

    float loss_acc = 0.0f;

    #pragma unroll 1
    for (int tile = blockIdx.x; tile < NTILES; tile += GRID) {
        const long row0 = (long)tile * TM;

        // ---- load x tile: fp16 hi split to SMEM, rn = sum x^2, s1 = sum|x-h| ----
        {
            const float4* xr = (const float4*)(x + (row0 + r2) * DIM + ch * 32);
            float rnp = 0.0f, s1p = 0.0f;
            #pragma unroll
            for (int j = 0; j < 8; j++) {
                float4 v = xr[j];
                rnp = fmaf(v.x, v.x, rnp); rnp = fmaf(v.y, v.y, rnp);
                rnp = fmaf(v.z, v.z, rnp); rnp = fmaf(v.w, v.w, rnp);
                __half h0 = __float2half_rn(v.x), h1 = __float2half_rn(v.y);
                __half h2 = __float2half_rn(v.z), h3 = __float2half_rn(v.w);
                s1p += fabsf(v.x - __half2float(h0)) + fabsf(v.y - __half2float(h1))
                     + fabsf(v.z - __half2float(h2)) + fabsf(v.w - __half2float(h3));
                int off = r2 * RSTRIDE + ch * 32 + j * 4;
                *(__half2*)(Ah + off)     = __halves2half2(h0, h1);
                *(__half2*)(Ah + off + 2) = __halves2half2(h2, h3);
            }
            float rno = __shfl_xor_sync(0xffffffffu, rnp, 1);
            float s1o = __shfl_xor_sync(0xffffffffu, s1p, 1);
            if (ch == 0) { rn_s[r2] = rnp + rno; s1_s[r2] = s1p + s1o; }
        }
        __syncthreads();

        // ---- stream 8 row-tiles of 16 against resident 64 codes (2 passes) ----
        #pragma unroll 1
        for (int rt = 0; rt < 8; rt++) {
            uint32_t aH[4][4];
            const uint32_t ab = aHbase0 + (uint32_t)(rt * 16) * (RSTRIDE * 2);
            #pragma unroll
            for (int kc = 0; kc < 4; kc++) LDSM4(aH[kc], ab + kc * 32);

            float f[8][4];
            #pragma unroll
            for (int nt = 0; nt < 8; nt++)
                #pragma unroll
                for (int q = 0; q < 4; q++) f[nt][q] = 0.0f;

            #pragma unroll
            for (int kc = 0; kc < 4; kc++) {
                #pragma unroll
                for (int nt = 0; nt < 8; nt++)
                    MMA16816(f[nt], aH[kc], BHf[nt >> 1][kc][(nt & 1) * 2], BHf[nt >> 1][kc][(nt & 1) * 2 + 1]);
                #pragma unroll
                for (int nt = 0; nt < 8; nt++)
                    MMA16816(f[nt], aH[kc], BMf[nt >> 1][kc][(nt & 1) * 2], BMf[nt >> 1][kc][(nt & 1) * 2 + 1]);
            }

            const float rn0 = rn_s[rt * 16 + crow];
            const float rn1 = rn_s[rt * 16 + 8 + crow];
            float b1_0 = FLT_MAX, b2_0 = FLT_MAX, b1_1 = FLT_MAX, b2_1 = FLT_MAX;
            int   k1_0 = 0, k1_1 = 0;

            #pragma unroll
            for (int nt = 0; nt < 8; nt++) {
                int n = w * 64 + nt * 8 + ccol;
                float d00 = fmaf(-2.0f, f[nt][0], rn0 + nk0_r[nt]);
                float d01 = fmaf(-2.0f, f[nt][1], rn0 + nk1_r[nt]);
                float d10 = fmaf(-2.0f, f[nt][2], rn1 + nk0_r[nt]);
                float d11 = fmaf(-2.0f, f[nt][3], rn1 + nk1_r[nt]);
                if (d00 < b1_0) { b2_0 = b1_0; b1_0 = d00; k1_0 = n; } else if (d00 < b2_0) b2_0 = d00;
                if (d01 < b1_0) { b2_0 = b1_0; b1_0 = d01; k1_0 = n + 1; } else if (d01 < b2_0) b2_0 = d01;
                if (d10 < b1_1) { b2_1 = b1_1; b1_1 = d10; k1_1 = n; } else if (d10 < b2_1) b2_1 = d10;
                if (d11 < b1_1) { b2_1 = b1_1; b1_1 = d11; k1_1 = n + 1; } else if (d11 < b2_1) b2_1 = d11;
            }

            // merge (b1,k1,b2) over lane bits 0-1
            #pragma unroll
            for (int off = 1; off <= 2; off <<= 1) {
                float ob1 = __shfl_xor_sync(0xffffffffu, b1_0, off);
                int   ok1 = __shfl_xor_sync(0xffffffffu, k1_0, off);
                float ob2 = __shfl_xor_sync(0xffffffffu, b2_0, off);
                float nb2 = fminf(fmaxf(b1_0, ob1), fminf(b2_0, ob2));
                if (ob1 < b1_0 || (ob1 == b1_0 && ok1 < k1_0)) { b1_0 = ob1; k1_0 = ok1; }
                b2_0 = nb2;
                float pb1 = __shfl_xor_sync(0xffffffffu, b1_1, off);
                int   pk1 = __shfl_xor_sync(0xffffffffu, k1_1, off);
                float pb2 = __shfl_xor_sync(0xffffffffu, b2_1, off);
                float mb2 = fminf(fmaxf(b1_1, pb1), fminf(b2_1, pb2));
                if (pb1 < b1_1 || (pb1 == b1_1 && pk1 < k1_1)) { b1_1 = pb1; k1_1 = pk1; }
                b2_1 = mb2;
            }
            if ((lane & 3) == 0) {
                int ra = rt * 16 + crow;
                rd1[ra * 8 + w] = b1_0;  rdk[ra * 8 + w] = k1_0;  rd2[ra * 8 + w] = b2_0;
                rd1[(ra + 8) * 8 + w] = b1_1;  rdk[(ra + 8) * 8 + w] = k1_1;  rd2[(ra + 8) * 8 + w] = b2_1;
            }
        }
        __syncthreads();

        // ---- cross-warp merge per row + margin flag ----
        if (tid < TM) {
            float b1 = rd1[tid * 8];
            int   k1 = rdk[tid * 8];
            float b2 = rd2[tid * 8];
            #pragma unroll
            for (int j = 1; j < 8; j++) {
                float c1 = rd1[tid * 8 + j];
                int   j1 = rdk[tid * 8 + j];
                float c2 = rd2[tid * 8 + j];
                float nb2 = fminf(fmaxf(b1, c1), fminf(b2, c2));
                if (c1 < b1 || (c1 == b1 && j1 < k1)) { b1 = c1; k1 = j1; }
                b2 = nb2;
            }
            codes_s[tid] = k1;
            // rigorous margin: |dist err| <= 2*0.05*sum|x-h| + rounding slack
            float thr = 0.2f * s1_s[tid] + 2e-4f;
            if (b2 - b1 <= thr) {
                int slot = atomicAdd(&g_wcount, 1);
                g_work[slot] = (int)(row0 + tid);
            } else {
                loss_acc += b1;
            }
        }
        __syncthreads();

        // ---- gather output: q = h + m (flagged rows rewritten by refine) ----
        {
            const int k = codes_s[r2];
            float4* dst = (float4*)(out + (row0 + r2) * DIM + ch * 32);
            #pragma unroll
            for (int j = 0; j < 8; j++) {
                int d0 = k * RSTRIDE + ch * 32 + j * 4;
                __half2 ha = *(const __half2*)(Bh + d0);
                __half2 hb = *(const __half2*)(Bh + d0 + 2);
                __half2 ma = *(const __half2*)(Bm + d0);
                __half2 mb = *(const __half2*)(Bm + d0 + 2);
                float2 fa = __half22float2(ha), fb = __half22float2(hb);
                float2 ga = __half22float2(ma), gb = __half22float2(mb);
                float4 o;
                o.x = fa.x + ga.x; o.y = fa.y + ga.y;
                o.z = fb.x + gb.x; o.w = fb.y + gb.y;
                dst[j] = o;
            }
        }
    }

    // ---- per-CTA loss reduction ----
    __syncthreads();
    float v = loss_acc;
    #pragma unroll
    for (int o = 16; o > 0; o >>= 1) v += __shfl_down_sync(0xffffffffu, v, o);
    if (lane == 0) rn_s[w] = v;
    __syncthreads();
    if (tid == 0) {
        float t = 0.0f;
        #pragma unroll
        for (int i = 0; i < 8; i++) t += rn_s[i];
        g_partials[blockIdx.x] = t;
    }
}

// ---------------------------------------------------------------------------
// Refine: exact fp32 re-decision for flagged rows (one warp per row).
// Accumulation order (d ascending) matches the R1 kernel that was bit-exact.
// ---------------------------------------------------------------------------
__global__ __launch_bounds__(256) void refine_kernel(
    const float* __restrict__ x, const float* __restrict__ dict,
    float* __restrict__ out)
{
    __shared__ float xrow[8][64];
    __shared__ float ns_s[NCODES];
    const int tid = threadIdx.x, w = tid >> 5, lane = tid & 31;
    for (int i = tid; i < NCODES; i += 256) ns_s[i] = g_ns[i];
    __syncthreads();

    const int nwarp = gridDim.x * 8;
    const int cnt = g_wcount;
    for (int i = blockIdx.x * 8 + w; i < cnt; i += nwarp) {
        const int row = g_work[i];
        float x0 = x[(long)row * 64 + lane];
        float x1 = x[(long)row * 64 + 32 + lane];
        xrow[w][lane] = x0; xrow[w][lane + 32] = x1;
        __syncwarp();
        float rn = fmaf(x0, x0, x1 * x1);
        #pragma unroll
        for (int o = 16; o > 0; o >>= 1) rn += __shfl_xor_sync(0xffffffffu, rn, o);

        float sim[16];
        #pragma unroll
        for (int c = 0; c < 16; c++) sim[c] = 0.0f;
        #pragma unroll 4
        for (int d = 0; d < 64; d++) {
            float xd = xrow[w][d];
            const float4* dp = (const float4*)(dict + d * NCODES + lane * 16);
            float4 q0 = dp[0], q1 = dp[1], q2 = dp[2], q3 = dp[3];
            sim[0]  = fmaf(xd, q0.x, sim[0]);  sim[1]  = fmaf(xd, q0.y, sim[1]);
            sim[2]  = fmaf(xd, q0.z, sim[2]);  sim[3]  = fmaf(xd, q0.w, sim[3]);
            sim[4]  = fmaf(xd, q1.x, sim[4]);  sim[5]  = fmaf(xd, q1.y, sim[5]);
            sim[6]  = fmaf(xd, q1.z, sim[6]);  sim[7]  = fmaf(xd, q1.w, sim[7]);
            sim[8]  = fmaf(xd, q2.x, sim[8]);  sim[9]  = fmaf(xd, q2.y, sim[9]);
            sim[10] = fmaf(xd, q2.z, sim[10]); sim[11] = fmaf(xd, q2.w, sim[11]);
            sim[12] = fmaf(xd, q3.x, sim[12]); sim[13] = fmaf(xd, q3.y, sim[13]);
            sim[14] = fmaf(xd, q3.z, sim[14]); sim[15] = fmaf(xd, q3.w, sim[15]);
        }
        float b1 = FLT_MAX; int k1 = 0;
        #pragma unroll
        for (int c = 0; c < 16; c++) {
            int k = lane * 16 + c;
            float dv = rn + ns_s[k] - 2.0f * sim[c];
            if (dv < b1) { b1 = dv; k1 = k; }
        }
        #pragma unroll
        for (int o = 16; o > 0; o >>= 1) {
            float ob = __shfl_xor_sync(0xffffffffu, b1, o);
            int   ok = __shfl_xor_sync(0xffffffffu, k1, o);
            if (ob < b1 || (ob == b1 && ok < k1)) { b1 = ob; k1 = ok; }
        }
        // rewrite output row with exact fp32 codeword
        out[(long)row * 64 + lane]      = dict[lane * NCODES + k1];
        out[(long)row * 64 + 32 + lane] = dict[(lane + 32) * NCODES + k1];
        if (lane == 0) atomicAdd(&g_refine_loss, b1);
        __syncwarp();
    }
}

__global__ __launch_bounds__(192) void finalize_kernel(float* __restrict__ out, int out_size) {
    const int tid = threadIdx.x;
    __shared__ float red[6];
    float s = (tid < GRID) ? g_partials[tid] : 0.0f;
    #pragma unroll
    for (int o = 16; o > 0; o >>= 1) s += __shfl_down_sync(0xffffffffu, s, o);
    if ((tid & 31) == 0) red[tid >> 5] = s;
    __syncthreads();
    if (tid == 0) {
        float t = g_refine_loss;
        #pragma unroll
        for (int i = 0; i < 6; i++) t += red[i];
        float m = t / (float)NELEM;
        if (out_size > NELEM) out[NELEM] = m + 0.25f * m;
    }
}

extern "C" void kernel_launch(void* const* d_in, const int* in_sizes, int n_in,
                              void* d_out, int out_size) {
    const float* x    = (const float*)d_in[0];   // [16,128,128,64]
    const float* dict = (const float*)d_in[1];   // [64,512]
    float* out = (float*)d_out;

    cudaFuncSetAttribute(vq_kernel, cudaFuncAttributeMaxDynamicSharedMemorySize, SM_SIZE);
    zero_kernel<<<1, 1>>>();
    vq_kernel<<<GRID, NTHREADS, SM_SIZE>>>(x, dict, out);
    refine_kernel<<<GRID, 256>>>(x, dict, out);
    finalize_kernel<<<1, 192>>>(out, out_size);
}

// round 10
// speedup vs baseline: 1.2188x; 1.2188x over previous
#include <cuda_runtime.h>
#include <cuda_fp16.h>
#include <float.h>
#include <stdint.h>

#define NROWS   262144
#define DIM     64
#define NCODES  512
#define NELEM   (NROWS * DIM)
#define TM      128
#define NTILES  (NROWS / TM)     // 2048
#define GRID    152
#define NTHREADS 320             // 8 compute warps + 2 loader warps

#define RSTRIDE_A 72             // halves per padded A row (144 B)
#define RSTRIDE_B 64             // halves per B row (128 B, unpadded)

// SMEM byte offsets
#define SM_AH    0               // A hi, 2 buffers x [128][72] f16  (36864)
#define SM_AM    36864           // A lo, 2 buffers                  (36864)
#define SM_BH    73728           // B hi [512][64] f16               (65536)
#define SM_BM    139264          // B lo                             (65536)
#define SM_NS    204800          // code norms f32[512]              (2048)
#define SM_RN    206848          // row norms, 2 x f32[128]          (1024)
#define SM_CODE  207872          // codes, 2 x int[128]              (1024)
#define SM_RD1   208896          // f32[128][8]                      (4096)
#define SM_RDK   212992          // int[128][8]                      (4096)
#define SM_SIZE  217088

#define ABUF_SZ  18432           // one A buffer (128*72*2)

__device__ float g_partials[GRID];

__device__ __forceinline__ uint32_t smem_u32(const void* p) {
    uint32_t a;
    asm("{ .reg .u64 t; cvta.to.shared.u64 t, %1; cvt.u32.u64 %0, t; }" : "=r"(a) : "l"(p));
    return a;
}

#define LDSM4(r, addr) \
    asm volatile("ldmatrix.sync.aligned.m8n8.x4.shared.b16 {%0,%1,%2,%3}, [%4];" \
        : "=r"((r)[0]), "=r"((r)[1]), "=r"((r)[2]), "=r"((r)[3]) : "r"(addr))

#define MMA16816(c, a, b0, b1) \
    asm volatile("mma.sync.aligned.m16n8k16.row.col.f32.f16.f16.f32 " \
        "{%0,%1,%2,%3}, {%4,%5,%6,%7}, {%8,%9}, {%0,%1,%2,%3};" \
        : "+f"((c)[0]), "+f"((c)[1]), "+f"((c)[2]), "+f"((c)[3]) \
        : "r"((a)[0]), "r"((a)[1]), "r"((a)[2]), "r"((a)[3]), "r"(b0), "r"(b1))

// named barriers: 3 = block-wide (320), 1 = compute-only (256)
#define BAR_ALL()  asm volatile("bar.sync 3, 320;" ::: "memory")
#define BAR_CMP()  asm volatile("bar.sync 1, 256;" ::: "memory")

extern __shared__ char smem_raw[];

__global__ __launch_bounds__(NTHREADS, 1) void vq_kernel(
    const float* __restrict__ x, const float* __restrict__ dict,
    float* __restrict__ out)
{
    char* sm = smem_raw;
    const uint32_t smu = smem_u32(sm);

    __half* Bh   = (__half*)(sm + SM_BH);
    __half* Bm   = (__half*)(sm + SM_BM);
    float*  ns_s = (float*)(sm + SM_NS);
    float*  rn_s = (float*)(sm + SM_RN);    // [2][128]
    int*    codes_s = (int*)(sm + SM_CODE); // [2][128]
    float*  rd1  = (float*)(sm + SM_RD1);
    int*    rdk  = (int*)(sm + SM_RDK);

    const int tid  = threadIdx.x;
    const int lane = tid & 31;

    // ---- build codebook splits (all 320 threads); dict is [D=64][K=512] ----
    {
        const float4* d4 = (const float4*)dict;
        for (int i = tid; i < 64 * 128; i += NTHREADS) {
            int d = i >> 7, kq = i & 127;
            float4 v = d4[d * 128 + kq];
            float vv[4] = {v.x, v.y, v.z, v.w};
            #pragma unroll
            for (int j = 0; j < 4; j++) {
                int k = kq * 4 + j;
                __half h = __float2half_rn(vv[j]);
                __half m = __float2half_rn(vv[j] - __half2float(h));
                Bh[k * RSTRIDE_B + d] = h;
                Bm[k * RSTRIDE_B + d] = m;
            }
        }
        for (int k = tid; k < NCODES; k += NTHREADS) {
            float s = 0.0f;
            #pragma unroll 8
            for (int d = 0; d < DIM; d++) {
                float v = dict[d * NCODES + k];
                s = fmaf(v, v, s);
            }
            ns_s[k] = s;
        }
    }
    __syncthreads();   // converged; last block-wide __syncthreads

    if (tid < 256) {
        // ================= COMPUTE WARPS =================
        const int w = tid >> 5;           // 0..7, owns codes [w*64, w*64+64)
        const int arow = (lane & 7) + (lane & 8);
        const int acol = (lane & 16) ? 8 : 0;
        const int bn   = (lane & 7) + ((lane & 16) >> 1);
        const int bk   = (lane & 8);
        const int crow = lane >> 2;
        const int ccol = 2 * (lane & 3);

        // B-stationary fragments in registers
        uint32_t BHf[4][4][4], BMf[4][4][4];
        {
            const uint32_t bHbase = smu + SM_BH + (uint32_t)((w * 64 + bn) * RSTRIDE_B + bk) * 2;
            const uint32_t bMbase = bHbase + (SM_BM - SM_BH);
            #pragma unroll
            for (int p = 0; p < 4; p++)
                #pragma unroll
                for (int kc = 0; kc < 4; kc++) {
                    uint32_t o = (uint32_t)(p * 16) * (RSTRIDE_B * 2) + kc * 32;
                    LDSM4(BHf[p][kc], bHbase + o);
                    LDSM4(BMf[p][kc], bMbase + o);
                }
        }
        const uint32_t aOff0 = (uint32_t)(arow * RSTRIDE_A + acol) * 2;

        float loss_acc = 0.0f;

        #pragma unroll 1
        for (int j = 0, tile = blockIdx.x; tile < NTILES; tile += GRID, j++) {
            BAR_ALL();                         // A[j&1], rn[j&1] ready
            const int b = j & 1;
            const uint32_t aBase = smu + (uint32_t)(b * ABUF_SZ) + aOff0;

            #pragma unroll 1
            for (int rt = 0; rt < 8; rt++) {
                const uint32_t ab = aBase + (uint32_t)(rt * 16) * (RSTRIDE_A * 2);

                float f[8][4];
                #pragma unroll
                for (int nt = 0; nt < 8; nt++)
                    #pragma unroll
                    for (int q = 0; q < 4; q++) f[nt][q] = 0.0f;

                #pragma unroll
                for (int kc = 0; kc < 4; kc++) {
                    uint32_t aH[4], aM[4];
                    LDSM4(aH, ab + kc * 32);
                    LDSM4(aM, ab + (SM_AM - SM_AH) + kc * 32);
                    #pragma unroll
                    for (int nt = 0; nt < 8; nt++)
                        MMA16816(f[nt], aH, BHf[nt >> 1][kc][(nt & 1) * 2], BHf[nt >> 1][kc][(nt & 1) * 2 + 1]);
                    #pragma unroll
                    for (int nt = 0; nt < 8; nt++)
                        MMA16816(f[nt], aM, BHf[nt >> 1][kc][(nt & 1) * 2], BHf[nt >> 1][kc][(nt & 1) * 2 + 1]);
                    #pragma unroll
                    for (int nt = 0; nt < 8; nt++)
                        MMA16816(f[nt], aH, BMf[nt >> 1][kc][(nt & 1) * 2], BMf[nt >> 1][kc][(nt & 1) * 2 + 1]);
                }

                const float rn0 = rn_s[b * 128 + rt * 16 + crow];
                const float rn1 = rn_s[b * 128 + rt * 16 + 8 + crow];
                float best0 = FLT_MAX, best1 = FLT_MAX;
                int   bk0 = 0, bk1 = 0;

                #pragma unroll
                for (int nt = 0; nt < 8; nt++) {
                    int n = w * 64 + nt * 8 + ccol;
                    float nk0 = ns_s[n], nk1 = ns_s[n + 1];
                    float d00 = fmaf(-2.0f, f[nt][0], rn0 + nk0);
                    float d01 = fmaf(-2.0f, f[nt][1], rn0 + nk1);
                    float d10 = fmaf(-2.0f, f[nt][2], rn1 + nk0);
                    float d11 = fmaf(-2.0f, f[nt][3], rn1 + nk1);
                    if (d00 < best0) { best0 = d00; bk0 = n; }
                    if (d01 < best0) { best0 = d01; bk0 = n + 1; }
                    if (d10 < best1) { best1 = d10; bk1 = n; }
                    if (d11 < best1) { best1 = d11; bk1 = n + 1; }
                }

                #pragma unroll
                for (int off = 1; off <= 2; off <<= 1) {
                    float od0 = __shfl_xor_sync(0xffffffffu, best0, off);
                    int   ok0 = __shfl_xor_sync(0xffffffffu, bk0, off);
                    if (od0 < best0 || (od0 == best0 && ok0 < bk0)) { best0 = od0; bk0 = ok0; }
                    float od1 = __shfl_xor_sync(0xffffffffu, best1, off);
                    int   ok1 = __shfl_xor_sync(0xffffffffu, bk1, off);
                    if (od1 < best1 || (od1 == best1 && ok1 < bk1)) { best1 = od1; bk1 = ok1; }
                }
                if ((lane & 3) == 0) {
                    int ra = rt * 16 + crow;
                    rd1[ra * 8 + w] = best0;        rdk[ra * 8 + w] = bk0;
                    rd1[(ra + 8) * 8 + w] = best1;  rdk[(ra + 8) * 8 + w] = bk1;
                }
            }
            BAR_CMP();                          // rd1/rdk complete (compute only)

            if (tid < TM) {
                float bd = rd1[tid * 8];
                int   bkk = rdk[tid * 8];
                #pragma unroll
                for (int q = 1; q < 8; q++) {
                    float dv = rd1[tid * 8 + q];
                    int   kk = rdk[tid * 8 + q];
                    if (dv < bd || (dv == bd && kk < bkk)) { bd = dv; bkk = kk; }
                }
                codes_s[b * 128 + tid] = bkk;
                loss_acc += bd;                 // ||x - q||^2 for this row
            }
        }
        BAR_ALL();                              // publish last codes to loaders

        // ---- per-CTA loss reduction (compute threads only) ----
        float v = loss_acc;
        #pragma unroll
        for (int o = 16; o > 0; o >>= 1) v += __shfl_down_sync(0xffffffffu, v, o);
        if (lane == 0) rd1[w] = v;
        BAR_CMP();
        if (tid == 0) {
            float t = 0.0f;
            #pragma unroll
            for (int i = 0; i < 8; i++) t += rd1[i];
            g_partials[blockIdx.x] = t;
        }
    } else {
        // ================= LOADER WARPS (tid 256..319) =================
        const int lt = tid - 256;               // 0..63, owns rows lt and lt+64
        __half* AhB = (__half*)(sm + SM_AH);
        __half* AmB = (__half*)(sm + SM_AM);

        // prologue: fill buffer 0 with tile blockIdx.x
        {
            const long row0 = (long)blockIdx.x * TM;
            #pragma unroll
            for (int s = 0; s < 2; s++) {
                int r = lt + s * 64;
                const float4* xr = (const float4*)(x + (row0 + r) * DIM);
                float rn = 0.0f;
                #pragma unroll
                for (int jj = 0; jj < 16; jj++) {
                    float4 v = xr[jj];
                    rn = fmaf(v.x, v.x, rn); rn = fmaf(v.y, v.y, rn);
                    rn = fmaf(v.z, v.z, rn); rn = fmaf(v.w, v.w, rn);
                    __half2 h01 = __floats2half2_rn(v.x, v.y);
                    __half2 h23 = __floats2half2_rn(v.z, v.w);
                    float2 hf01 = __half22float2(h01), hf23 = __half22float2(h23);
                    __half2 m01 = __floats2half2_rn(v.x - hf01.x, v.y - hf01.y);
                    __half2 m23 = __floats2half2_rn(v.z - hf23.x, v.w - hf23.y);
                    int off = r * RSTRIDE_A + jj * 4;
                    *(__half2*)(AhB + off)     = h01;
                    *(__half2*)(AhB + off + 2) = h23;
                    *(__half2*)(AmB + off)     = m01;
                    *(__half2*)(AmB + off + 2) = m23;
                }
                rn_s[r] = rn;
            }
        }

        long prev_row0 = 0;
        #pragma unroll 1
        for (int j = 0, tile = blockIdx.x; tile < NTILES; tile += GRID, j++) {
            BAR_ALL();
            // load tile j+1 into buffer (j+1)&1 (overlaps compute of tile j)
            const int nb = (j + 1) & 1;
            const int nt_tile = tile + GRID;
            if (nt_tile < NTILES) {
                const long row0n = (long)nt_tile * TM;
                __half* Ah = AhB + nb * (ABUF_SZ / 2);
                __half* Am = AmB + nb * (ABUF_SZ / 2);
                #pragma unroll
                for (int s = 0; s < 2; s++) {
                    int r = lt + s * 64;
                    const float4* xr = (const float4*)(x + (row0n + r) * DIM);
                    float rn = 0.0f;
                    #pragma unroll
                    for (int jj = 0; jj < 16; jj++) {
                        float4 v = xr[jj];
                        rn = fmaf(v.x, v.x, rn); rn = fmaf(v.y, v.y, rn);
                        rn = fmaf(v.z, v.z, rn); rn = fmaf(v.w, v.w, rn);
                        __half2 h01 = __floats2half2_rn(v.x, v.y);
                        __half2 h23 = __floats2half2_rn(v.z, v.w);
                        float2 hf01 = __half22float2(h01), hf23 = __half22float2(h23);
                        __half2 m01 = __floats2half2_rn(v.x - hf01.x, v.y - hf01.y);
                        __half2 m23 = __floats2half2_rn(v.z - hf23.x, v.w - hf23.y);
                        int off = r * RSTRIDE_A + jj * 4;
                        *(__half2*)(Ah + off)     = h01;
                        *(__half2*)(Ah + off + 2) = h23;
                        *(__half2*)(Am + off)     = m01;
                        *(__half2*)(Am + off + 2) = m23;
                    }
                    rn_s[nb * 128 + r] = rn;
                }
            }
            // gather output of tile j-1 (codes published at BAR_ALL above)
            if (j > 0) {
                const int pb = (j - 1) & 1;
                #pragma unroll
                for (int s = 0; s < 2; s++) {
                    int r = lt + s * 64;
                    int k = codes_s[pb * 128 + r];
                    const __half2* bh = (const __half2*)(Bh + k * RSTRIDE_B);
                    const __half2* bm = (const __half2*)(Bm + k * RSTRIDE_B);
                    float4* dst = (float4*)(out + (prev_row0 + r) * DIM);
                    #pragma unroll
                    for (int jj = 0; jj < 16; jj++) {
                        float2 fa = __half22float2(bh[jj * 2]);
                        float2 fb = __half22float2(bh[jj * 2 + 1]);
                        float2 ga = __half22float2(bm[jj * 2]);
                        float2 gb = __half22float2(bm[jj * 2 + 1]);
                        float4 o;
                        o.x = fa.x + ga.x; o.y = fa.y + ga.y;
                        o.z = fb.x + gb.x; o.w = fb.y + gb.y;
                        dst[jj] = o;
                    }
                }
            }
            prev_row0 = (long)tile * TM;
        }
        BAR_ALL();                              // last tile's codes published
        // final gather
        {
            int nt_total = (NTILES - 1 - blockIdx.x) / GRID;   // T-1
            const int pb = nt_total & 1;
            #pragma unroll
            for (int s = 0; s < 2; s++) {
                int r = lt + s * 64;
                int k = codes_s[pb * 128 + r];
                const __half2* bh = (const __half2*)(Bh + k * RSTRIDE_B);
                const __half2* bm = (const __half2*)(Bm + k * RSTRIDE_B);
                float4* dst = (float4*)(out + (prev_row0 + r) * DIM);
                #pragma unroll
                for (int jj = 0; jj < 16; jj++) {
                    float2 fa = __half22float2(bh[jj * 2]);
                    float2 fb = __half22float2(bh[jj * 2 + 1]);
                    float2 ga = __half22float2(bm[jj * 2]);
                    float2 gb = __half22float2(bm[jj * 2 + 1]);
                    float4 o;
                    o.x = fa.x + ga.x; o.y = fa.y + ga.y;
                    o.z = fb.x + gb.x; o.w = fb.y + gb.y;
                    dst[jj] = o;
                }
            }
        }
    }
}

__global__ __launch_bounds__(192) void finalize_kernel(float* __restrict__ out, int out_size) {
    const int tid = threadIdx.x;
    __shared__ float red[6];
    float s = (tid < GRID) ? g_partials[tid] : 0.0f;
    #pragma unroll
    for (int o = 16; o > 0; o >>= 1) s += __shfl_down_sync(0xffffffffu, s, o);
    if ((tid & 31) == 0) red[tid >> 5] = s;
    __syncthreads();
    if (tid == 0) {
        float t = 0.0f;
        #pragma unroll
        for (int i = 0; i < 6; i++) t += red[i];
        float m = t / (float)NELEM;
        if (out_size > NELEM) out[NELEM] = m + 0.25f * m;
    }
}

extern "C" void kernel_launch(void* const* d_in, const int* in_sizes, int n_in,
                              void* d_out, int out_size) {
    const float* x    = (const float*)d_in[0];   // [16,128,128,64]
    const float* dict = (const float*)d_in[1];   // [64,512]
    float* out = (float*)d_out;

    cudaFuncSetAttribute(vq_kernel, cudaFuncAttributeMaxDynamicSharedMemorySize, SM_SIZE);
    vq_kernel<<<GRID, NTHREADS, SM_SIZE>>>(x, dict, out);
    finalize_kernel<<<1, 192>>>(out, out_size);
}